// round 2
// baseline (speedup 1.0000x reference)
#include <cuda_runtime.h>
#include <cstddef>

#define IMG_W 256
#define IMG_H 256
#define RPB   128              // output rows per warp-strip
#define STEPS (RPB + 8)        // input rows S-4 .. S+RPB+3

// edge = conv(x,K5)+conv(x,K3) == 2.2*x - 0.19*box3(x) - 0.01*box5(x)
// out  = |maxpool5x5_s1_p2(edge)|  (separable; -inf pool padding)
//
// One warp per (plane, 128-row strip); lane l owns 8 columns. No smem, no
// block barriers: horizontal halos via warp shuffles, vertical state in
// register rings with static mod-5 indices (unroll-by-5).

__global__ void __launch_bounds__(64)
fused_edge_pool(const float* __restrict__ x, float* __restrict__ out)
{
    const int lane  = threadIdx.x & 31;
    const int g     = blockIdx.x * 2 + (threadIdx.x >> 5);   // warp id, 0..1023
    const int plane = g >> 1;                                // 512 planes
    const int S     = (g & 1) ? RPB : 0;
    const int c0    = lane << 3;

    const float* __restrict__ xp = x   + (size_t)plane * (IMG_H * IMG_W) + c0;
    float*       __restrict__ op = out + (size_t)plane * (IMG_H * IMG_W) + c0;

    const float    NINF = __int_as_float(0xff800000);
    const unsigned FULL = 0xffffffffu;

    // Register rings (depth 5; all indices static after unroll-by-5).
    float h3r[5][8], h5r[5][8], xr[5][8], hmr[5][8];
#pragma unroll
    for (int i = 0; i < 5; ++i)
#pragma unroll
        for (int j = 0; j < 8; ++j) {
            h3r[i][j] = 0.f; h5r[i][j] = 0.f; xr[i][j] = 0.f; hmr[i][j] = NINF;
        }

    // 3-deep prefetch shift chain (MOVs renamed away in unrolled code).
    float4 n1a, n1b, n2a, n2b, n3a, n3b;
    {
        const float4 z = make_float4(0.f, 0.f, 0.f, 0.f);
        int r0 = S - 4, r1 = S - 3, r2 = S - 2;
        n1a = ((unsigned)r0 < IMG_H) ? *reinterpret_cast<const float4*>(xp + r0 * IMG_W)     : z;
        n1b = ((unsigned)r0 < IMG_H) ? *reinterpret_cast<const float4*>(xp + r0 * IMG_W + 4) : z;
        n2a = ((unsigned)r1 < IMG_H) ? *reinterpret_cast<const float4*>(xp + r1 * IMG_W)     : z;
        n2b = ((unsigned)r1 < IMG_H) ? *reinterpret_cast<const float4*>(xp + r1 * IMG_W + 4) : z;
        n3a = ((unsigned)r2 < IMG_H) ? *reinterpret_cast<const float4*>(xp + r2 * IMG_W)     : z;
        n3b = ((unsigned)r2 < IMG_H) ? *reinterpret_cast<const float4*>(xp + r2 * IMG_W + 4) : z;
    }

#pragma unroll 1
    for (int ss = 0; ss < STEPS; ss += 5) {
#pragma unroll
        for (int k = 0; k < 5; ++k) {
            const int s = ss + k;
            if (s >= STEPS) break;          // uniform across warp
            const int rin = S - 4 + s;      // input row consumed this step

            const float4 xa = n1a, xb = n1b;
            n1a = n2a; n1b = n2b; n2a = n3a; n2b = n3b;
            {
                const int rl = rin + 3;     // prefetch distance 3
                const bool v = ((unsigned)rl < IMG_H) && (s + 3 < STEPS);
                const float4 z = make_float4(0.f, 0.f, 0.f, 0.f);
                n3a = v ? *reinterpret_cast<const float4*>(xp + rl * IMG_W)     : z;
                n3b = v ? *reinterpret_cast<const float4*>(xp + rl * IMG_W + 4) : z;
            }

            // ---- horizontal box sums (halo via shuffles) ----
            float w[12];
            w[2] = xa.x; w[3] = xa.y; w[4] = xa.z; w[5] = xa.w;
            w[6] = xb.x; w[7] = xb.y; w[8] = xb.z; w[9] = xb.w;
            w[0]  = __shfl_up_sync(FULL, xb.z, 1);      // left nbr col6 -> c0-2
            w[1]  = __shfl_up_sync(FULL, xb.w, 1);      // left nbr col7 -> c0-1
            w[10] = __shfl_down_sync(FULL, xa.x, 1);    // right nbr col0 -> c0+8
            w[11] = __shfl_down_sync(FULL, xa.y, 1);    // right nbr col1 -> c0+9
            if (lane == 0)  { w[0]  = 0.f; w[1]  = 0.f; }   // image edge: zero pad
            if (lane == 31) { w[10] = 0.f; w[11] = 0.f; }

#pragma unroll
            for (int j = 0; j < 8; ++j) {
                const float a3 = w[j + 1] + w[j + 2] + w[j + 3];
                h3r[k][j] = a3;
                h5r[k][j] = a3 + w[j] + w[j + 4];
                xr[k][j]  = w[j + 2];
            }

            // ---- edge row re = rin-2 (vertical box sums) ----
            const int i1 = (k + 2) % 5, i2 = (k + 3) % 5, i3 = (k + 4) % 5;
            float e[8];
#pragma unroll
            for (int j = 0; j < 8; ++j) {
                const float s3 = h3r[i1][j] + h3r[i2][j] + h3r[i3][j];
                const float s5 = (h5r[0][j] + h5r[1][j]) + (h5r[2][j] + h5r[3][j]) + h5r[4][j];
                e[j] = 2.2f * xr[i2][j] - 0.19f * s3 - 0.01f * s5;
            }

            // ---- horizontal 5-max of edge row (halo via shuffles) ----
            float q[12];
            q[0]  = __shfl_up_sync(FULL, e[6], 1);
            q[1]  = __shfl_up_sync(FULL, e[7], 1);
            q[10] = __shfl_down_sync(FULL, e[0], 1);
            q[11] = __shfl_down_sync(FULL, e[1], 1);
            if (lane == 0)  { q[0]  = NINF; q[1]  = NINF; }  // pool -inf pad
            if (lane == 31) { q[10] = NINF; q[11] = NINF; }
#pragma unroll
            for (int j = 0; j < 8; ++j) q[j + 2] = e[j];

            const int  re  = rin - 2;
            const bool val = (re >= 0 && re < IMG_H);
#pragma unroll
            for (int j = 0; j < 8; ++j) {
                const float m = fmaxf(fmaxf(fmaxf(q[j], q[j + 1]),
                                            fmaxf(q[j + 2], q[j + 3])), q[j + 4]);
                hmr[k][j] = val ? m : NINF;
            }

            // ---- vertical 5-max + abs, output row r = rin-4 ----
            if (s >= 8) {
                const int r = rin - 4;
                float o[8];
#pragma unroll
                for (int j = 0; j < 8; ++j)
                    o[j] = fabsf(fmaxf(fmaxf(fmaxf(hmr[0][j], hmr[1][j]),
                                             fmaxf(hmr[2][j], hmr[3][j])), hmr[4][j]));
                *reinterpret_cast<float4*>(op + r * IMG_W)     = make_float4(o[0], o[1], o[2], o[3]);
                *reinterpret_cast<float4*>(op + r * IMG_W + 4) = make_float4(o[4], o[5], o[6], o[7]);
            }
        }
    }
}

extern "C" void kernel_launch(void* const* d_in, const int* in_sizes, int n_in,
                              void* d_out, int out_size)
{
    const float* x = (const float*)d_in[0];
    float* out = (float*)d_out;
    const int planes = in_sizes[0] / (IMG_H * IMG_W);          // 512
    const int warps  = planes * (IMG_H / RPB);                 // 1024
    fused_edge_pool<<<warps / 2, 64>>>(x, out);                // 2 warps/block
}